// round 1
// baseline (speedup 1.0000x reference)
#include <cuda_runtime.h>
#include <cuda_bf16.h>
#include <math.h>

// ---------------------------------------------------------------------------
// Problem dimensions (compile-time)
// ---------------------------------------------------------------------------
#define D_MODEL   768
#define D_STATE   64
#define D_CONV    4
#define D_SSM     1536
#define HEADDIM   64
#define NHEADS    24            // D_SSM / HEADDIM
#define CONV_DIM  1664          // D_SSM + 2*D_STATE
#define D_IN_PROJ 3224          // 2*D_SSM + 2*D_STATE + NHEADS
#define BB        2
#define LL        512
#define BL        (BB*LL)       // 1024

#define DT_OFF    (D_SSM + CONV_DIM)   // 3200

// ---------------------------------------------------------------------------
// Scratch (static device globals — no allocation allowed)
// ---------------------------------------------------------------------------
__device__ float g_zxbcdt[BL * D_IN_PROJ];   // in_proj output [BL, 3224]
__device__ float g_xbc[BL * CONV_DIM];       // conv+silu output [BL, 1664]
__device__ float g_dt[BL * NHEADS];
__device__ float g_dA[BL * NHEADS];
__device__ float g_y[BL * D_SSM];            // gated scan output [BL, 1536]

// ---------------------------------------------------------------------------
// SGEMM:  C[m,n] = sum_k A[m,k] * W[n,k]
//   A: [M,K] row-major, W: [N,K] row-major (both K-major), C: [M,N] row-major
// ---------------------------------------------------------------------------
template<int BM, int BN, int BK, int TM, int TN>
__global__ __launch_bounds__(256) void sgemm_tn(
    const float* __restrict__ A, const float* __restrict__ W,
    float* __restrict__ C, int M, int N, int K)
{
    constexpr int TX = BN / TN;   // threads along n
    constexpr int TY = BM / TM;   // threads along m
    static_assert(TX * TY == 256, "thread grid");

    __shared__ float As[BK][BM + 4];
    __shared__ float Ws[BK][BN + 4];

    const int tid = threadIdx.x;
    const int tx  = tid % TX;
    const int ty  = tid / TX;
    const int m0  = blockIdx.y * BM;
    const int n0  = blockIdx.x * BN;

    float acc[TM][TN];
#pragma unroll
    for (int i = 0; i < TM; i++)
#pragma unroll
        for (int j = 0; j < TN; j++) acc[i][j] = 0.f;

    constexpr int AF4 = BM * BK / 4;
    constexpr int WF4 = BN * BK / 4;
    constexpr int C4R = BK / 4;   // float4 per row of a tile

    for (int kt = 0; kt < K; kt += BK) {
        // --- stage A tile (transposed into As[k][m]) ---
#pragma unroll
        for (int i = tid; i < AF4; i += 256) {
            int row = i / C4R, c4 = i % C4R;
            float4 v = *(const float4*)(A + (size_t)(m0 + row) * K + kt + c4 * 4);
            As[c4 * 4 + 0][row] = v.x;
            As[c4 * 4 + 1][row] = v.y;
            As[c4 * 4 + 2][row] = v.z;
            As[c4 * 4 + 3][row] = v.w;
        }
        // --- stage W tile (transposed into Ws[k][n]) ---
#pragma unroll
        for (int i = tid; i < WF4; i += 256) {
            int row = i / C4R, c4 = i % C4R;
            int n = n0 + row;
            float4 v = make_float4(0.f, 0.f, 0.f, 0.f);
            if (n < N) v = *(const float4*)(W + (size_t)n * K + kt + c4 * 4);
            Ws[c4 * 4 + 0][row] = v.x;
            Ws[c4 * 4 + 1][row] = v.y;
            Ws[c4 * 4 + 2][row] = v.z;
            Ws[c4 * 4 + 3][row] = v.w;
        }
        __syncthreads();

#pragma unroll
        for (int k = 0; k < BK; k++) {
            float a[TM], b[TN];
#pragma unroll
            for (int i = 0; i < TM; i++) a[i] = As[k][ty * TM + i];
#pragma unroll
            for (int j = 0; j < TN; j++) b[j] = Ws[k][tx * TN + j];
#pragma unroll
            for (int i = 0; i < TM; i++)
#pragma unroll
                for (int j = 0; j < TN; j++)
                    acc[i][j] = fmaf(a[i], b[j], acc[i][j]);
        }
        __syncthreads();
    }

#pragma unroll
    for (int i = 0; i < TM; i++) {
        int m = m0 + ty * TM + i;
#pragma unroll
        for (int j = 0; j < TN; j++) {
            int n = n0 + tx * TN + j;
            if (m < M && n < N) C[(size_t)m * N + n] = acc[i][j];
        }
    }
}

// ---------------------------------------------------------------------------
// Depthwise causal conv (width 4) + bias + SiLU over the xBC slice of zxbcdt
// ---------------------------------------------------------------------------
__global__ void conv_silu_kernel(const float* __restrict__ zx,
                                 const float* __restrict__ cw,
                                 const float* __restrict__ cb,
                                 float* __restrict__ out)
{
    int idx = blockIdx.x * blockDim.x + threadIdx.x;
    if (idx >= BL * CONV_DIM) return;
    int c  = idx % CONV_DIM;
    int bl = idx / CONV_DIM;
    int l  = bl % LL;
    int b  = bl / LL;

    float sum = cb[c];
#pragma unroll
    for (int j = 0; j < D_CONV; j++) {
        int t = l + j - (D_CONV - 1);
        if (t >= 0)
            sum = fmaf(zx[(size_t)(b * LL + t) * D_IN_PROJ + D_SSM + c],
                       cw[c * D_CONV + j], sum);
    }
    float sig = 1.f / (1.f + expf(-sum));
    out[idx] = sum * sig;
}

// ---------------------------------------------------------------------------
// dt = clip(softplus(dt_raw + dt_bias), 1e-6, 1000)
// dA = clip(exp(dt * (-exp(A_log))), 1e-6, 1000)
// ---------------------------------------------------------------------------
__global__ void dtda_kernel(const float* __restrict__ zx,
                            const float* __restrict__ dt_bias,
                            const float* __restrict__ A_log,
                            float* __restrict__ dt_out,
                            float* __restrict__ dA_out)
{
    int idx = blockIdx.x * blockDim.x + threadIdx.x;
    if (idx >= BL * NHEADS) return;
    int h  = idx % NHEADS;
    int bl = idx / NHEADS;

    float raw = zx[(size_t)bl * D_IN_PROJ + DT_OFF + h] + dt_bias[h];
    // stable softplus: max(x,0) + log1p(exp(-|x|))
    float sp = fmaxf(raw, 0.f) + log1pf(expf(-fabsf(raw)));
    float dt = fminf(fmaxf(sp, 1e-6f), 1000.f);
    float A  = -expf(A_log[h]);
    float dA = fminf(fmaxf(expf(dt * A), 1e-6f), 1000.f);
    dt_out[idx] = dt;
    dA_out[idx] = dA;
}

// ---------------------------------------------------------------------------
// Sequential SSM scan.  One block per (b,h); 256 threads.
// thread tid: p = tid>>2 (headdim index), ng = tid&3 (16-wide state slice).
// State [64 x 64] lives in registers: 16 floats/thread.  No __syncthreads in
// the time loop; y-reduction over the state dim uses shfl within each quad.
// Fuses y = (state . C + D*x) * silu(z).
// ---------------------------------------------------------------------------
__device__ __forceinline__ float clamp1k(float v) {
    return fminf(fmaxf(v, -1000.f), 1000.f);
}

__global__ __launch_bounds__(256) void scan_kernel(
    const float* __restrict__ xbc, const float* __restrict__ dtb,
    const float* __restrict__ dab, const float* __restrict__ Dp,
    const float* __restrict__ zx,  float* __restrict__ yout)
{
    const int bh = blockIdx.x;
    const int b  = bh / NHEADS;
    const int h  = bh % NHEADS;
    const int tid = threadIdx.x;
    const int p  = tid >> 2;
    const int ng = tid & 3;

    float s[16];
#pragma unroll
    for (int i = 0; i < 16; i++) s[i] = 0.f;
    const float Dv = Dp[h];

    for (int t = 0; t < LL; t++) {
        const size_t rbase = (size_t)(b * LL + t);
        const float* row = xbc + rbase * CONV_DIM;
        const float xv  = row[h * HEADDIM + p];
        const int   bt  = (b * LL + t) * NHEADS + h;
        const float dtv = dtb[bt];
        const float dav = dab[bt];
        const float dtx = dtv * xv;

        const float4* B4 = (const float4*)(row + D_SSM) + ng * 4;
        const float4* C4 = (const float4*)(row + D_SSM + D_STATE) + ng * 4;

        float a0 = 0.f, a1 = 0.f, a2 = 0.f, a3 = 0.f;
#pragma unroll
        for (int i = 0; i < 4; i++) {
            float4 Bv = B4[i];
            float4 Cv = C4[i];
            int j = i * 4;
            s[j + 0] = clamp1k(fmaf(s[j + 0], dav, dtx * Bv.x));
            a0 = fmaf(s[j + 0], Cv.x, a0);
            s[j + 1] = clamp1k(fmaf(s[j + 1], dav, dtx * Bv.y));
            a1 = fmaf(s[j + 1], Cv.y, a1);
            s[j + 2] = clamp1k(fmaf(s[j + 2], dav, dtx * Bv.z));
            a2 = fmaf(s[j + 2], Cv.z, a2);
            s[j + 3] = clamp1k(fmaf(s[j + 3], dav, dtx * Bv.w));
            a3 = fmaf(s[j + 3], Cv.w, a3);
        }
        float accv = (a0 + a1) + (a2 + a3);
        accv += __shfl_xor_sync(0xffffffffu, accv, 1);
        accv += __shfl_xor_sync(0xffffffffu, accv, 2);

        if (ng == 0) {
            float zv  = zx[rbase * D_IN_PROJ + h * HEADDIM + p];
            float sig = 1.f / (1.f + expf(-zv));
            float yv  = fmaf(Dv, xv, accv);
            yout[rbase * D_SSM + h * HEADDIM + p] = yv * zv * sig;
        }
    }
}

// ---------------------------------------------------------------------------
// Launch
// ---------------------------------------------------------------------------
extern "C" void kernel_launch(void* const* d_in, const int* in_sizes, int n_in,
                              void* d_out, int out_size)
{
    const float* u       = (const float*)d_in[0];  // [B,L,768]
    const float* W_in    = (const float*)d_in[1];  // [3224,768]
    const float* conv_w  = (const float*)d_in[2];  // [1664,4]
    const float* conv_b  = (const float*)d_in[3];  // [1664]
    const float* dt_bias = (const float*)d_in[4];  // [24]
    const float* A_log   = (const float*)d_in[5];  // [24]
    const float* D_param = (const float*)d_in[6];  // [24]
    const float* W_out   = (const float*)d_in[7];  // [768,1536]
    float* out = (float*)d_out;                    // [B,L,768]

    float *zx, *xbc, *dt, *dA, *y;
    cudaGetSymbolAddress((void**)&zx,  g_zxbcdt);
    cudaGetSymbolAddress((void**)&xbc, g_xbc);
    cudaGetSymbolAddress((void**)&dt,  g_dt);
    cudaGetSymbolAddress((void**)&dA,  g_dA);
    cudaGetSymbolAddress((void**)&y,   g_y);

    // 1) in_proj: [1024,768] x [3224,768]^T -> [1024,3224]
    {
        dim3 grid((D_IN_PROJ + 63) / 64, BL / 128);
        sgemm_tn<128, 64, 16, 8, 4><<<grid, 256>>>(u, W_in, zx, BL, D_IN_PROJ, D_MODEL);
    }
    // 2) depthwise conv + bias + silu
    {
        int cnt = BL * CONV_DIM;
        conv_silu_kernel<<<(cnt + 255) / 256, 256>>>(zx, conv_w, conv_b, xbc);
    }
    // 3) dt / dA prep
    {
        int cnt = BL * NHEADS;
        dtda_kernel<<<(cnt + 255) / 256, 256>>>(zx, dt_bias, A_log, dt, dA);
    }
    // 4) sequential scan + gating
    scan_kernel<<<BB * NHEADS, 256>>>(xbc, dt, dA, D_param, zx, y);

    // 5) out_proj: [1024,1536] x [768,1536]^T -> [1024,768]
    {
        dim3 grid(D_MODEL / 64, BL / 64);
        sgemm_tn<64, 64, 16, 4, 4><<<grid, 256>>>(y, W_out, out, BL, D_MODEL, D_SSM);
    }
}

// round 2
// speedup vs baseline: 2.2571x; 2.2571x over previous
#include <cuda_runtime.h>
#include <cuda_bf16.h>
#include <math.h>

// ---------------------------------------------------------------------------
// Problem dimensions (compile-time)
// ---------------------------------------------------------------------------
#define D_MODEL   768
#define D_STATE   64
#define D_CONV    4
#define D_SSM     1536
#define HEADDIM   64
#define NHEADS    24            // D_SSM / HEADDIM
#define CONV_DIM  1664          // D_SSM + 2*D_STATE
#define D_IN_PROJ 3224          // 2*D_SSM + 2*D_STATE + NHEADS
#define BB        2
#define LL        512
#define BL        (BB*LL)       // 1024
#define QC        64            // chunk length
#define NCHUNK    (LL/QC)       // 8
#define NBHC      (BB*NHEADS*NCHUNK)  // 384

#define DT_OFF    (D_SSM + CONV_DIM)   // 3200
#define LOG1EM6   (-13.815510558f)

// ---------------------------------------------------------------------------
// Scratch (static device globals — no allocation allowed)
// ---------------------------------------------------------------------------
__device__ float g_zxbcdt[BL * D_IN_PROJ];   // in_proj output [BL, 3224]
__device__ float g_xbc[BL * CONV_DIM];       // conv+silu output [BL, 1664]
__device__ float g_dt[BL * NHEADS];
__device__ float g_ldA[BL * NHEADS];         // log(dA) (clip folded in)
__device__ float g_y[BL * D_SSM];            // scan output [BL, 1536]
__device__ float g_T[NBHC * HEADDIM * D_STATE];   // per-chunk state contribution
__device__ float g_S[NBHC * HEADDIM * D_STATE];   // state entering each chunk
__device__ float g_ai[NBHC * QC];            // exp(la_i) per position
__device__ float g_laend[NBHC];              // la at chunk end

// ---------------------------------------------------------------------------
// SGEMM:  C[m,n] = sum_k A[m,k] * W[n,k]
// ---------------------------------------------------------------------------
template<int BM, int BN, int BK, int TM, int TN>
__global__ __launch_bounds__(256) void sgemm_tn(
    const float* __restrict__ A, const float* __restrict__ W,
    float* __restrict__ C, int M, int N, int K)
{
    constexpr int TX = BN / TN;
    constexpr int TY = BM / TM;
    static_assert(TX * TY == 256, "thread grid");

    __shared__ float As[BK][BM + 4];
    __shared__ float Ws[BK][BN + 4];

    const int tid = threadIdx.x;
    const int tx  = tid % TX;
    const int ty  = tid / TX;
    const int m0  = blockIdx.y * BM;
    const int n0  = blockIdx.x * BN;

    float acc[TM][TN];
#pragma unroll
    for (int i = 0; i < TM; i++)
#pragma unroll
        for (int j = 0; j < TN; j++) acc[i][j] = 0.f;

    constexpr int AF4 = BM * BK / 4;
    constexpr int WF4 = BN * BK / 4;
    constexpr int C4R = BK / 4;

    for (int kt = 0; kt < K; kt += BK) {
#pragma unroll
        for (int i = tid; i < AF4; i += 256) {
            int row = i / C4R, c4 = i % C4R;
            float4 v = *(const float4*)(A + (size_t)(m0 + row) * K + kt + c4 * 4);
            As[c4 * 4 + 0][row] = v.x;
            As[c4 * 4 + 1][row] = v.y;
            As[c4 * 4 + 2][row] = v.z;
            As[c4 * 4 + 3][row] = v.w;
        }
#pragma unroll
        for (int i = tid; i < WF4; i += 256) {
            int row = i / C4R, c4 = i % C4R;
            int n = n0 + row;
            float4 v = make_float4(0.f, 0.f, 0.f, 0.f);
            if (n < N) v = *(const float4*)(W + (size_t)n * K + kt + c4 * 4);
            Ws[c4 * 4 + 0][row] = v.x;
            Ws[c4 * 4 + 1][row] = v.y;
            Ws[c4 * 4 + 2][row] = v.z;
            Ws[c4 * 4 + 3][row] = v.w;
        }
        __syncthreads();

#pragma unroll
        for (int k = 0; k < BK; k++) {
            float a[TM], b[TN];
#pragma unroll
            for (int i = 0; i < TM; i++) a[i] = As[k][ty * TM + i];
#pragma unroll
            for (int j = 0; j < TN; j++) b[j] = Ws[k][tx * TN + j];
#pragma unroll
            for (int i = 0; i < TM; i++)
#pragma unroll
                for (int j = 0; j < TN; j++)
                    acc[i][j] = fmaf(a[i], b[j], acc[i][j]);
        }
        __syncthreads();
    }

#pragma unroll
    for (int i = 0; i < TM; i++) {
        int m = m0 + ty * TM + i;
#pragma unroll
        for (int j = 0; j < TN; j++) {
            int n = n0 + tx * TN + j;
            if (m < M && n < N) C[(size_t)m * N + n] = acc[i][j];
        }
    }
}

// ---------------------------------------------------------------------------
// Depthwise causal conv (width 4) + bias + SiLU
// ---------------------------------------------------------------------------
__global__ void conv_silu_kernel(const float* __restrict__ zx,
                                 const float* __restrict__ cw,
                                 const float* __restrict__ cb,
                                 float* __restrict__ out)
{
    int idx = blockIdx.x * blockDim.x + threadIdx.x;
    if (idx >= BL * CONV_DIM) return;
    int c  = idx % CONV_DIM;
    int bl = idx / CONV_DIM;
    int l  = bl % LL;
    int b  = bl / LL;

    float sum = cb[c];
#pragma unroll
    for (int j = 0; j < D_CONV; j++) {
        int t = l + j - (D_CONV - 1);
        if (t >= 0)
            sum = fmaf(zx[(size_t)(b * LL + t) * D_IN_PROJ + D_SSM + c],
                       cw[c * D_CONV + j], sum);
    }
    float sig = 1.f / (1.f + expf(-sum));
    out[idx] = sum * sig;
}

// ---------------------------------------------------------------------------
// dt = clip(softplus(dt_raw + dt_bias), 1e-6, 1000)
// ldA = max(dt * (-exp(A_log)), ln 1e-6)   (exact log of clipped dA)
// ---------------------------------------------------------------------------
__global__ void dtda_kernel(const float* __restrict__ zx,
                            const float* __restrict__ dt_bias,
                            const float* __restrict__ A_log,
                            float* __restrict__ dt_out,
                            float* __restrict__ ldA_out)
{
    int idx = blockIdx.x * blockDim.x + threadIdx.x;
    if (idx >= BL * NHEADS) return;
    int h  = idx % NHEADS;
    int bl = idx / NHEADS;

    float raw = zx[(size_t)bl * D_IN_PROJ + DT_OFF + h] + dt_bias[h];
    float sp = fmaxf(raw, 0.f) + log1pf(expf(-fabsf(raw)));
    float dt = fminf(fmaxf(sp, 1e-6f), 1000.f);
    float A  = -expf(A_log[h]);
    dt_out[idx]  = dt;
    ldA_out[idx] = fmaxf(dt * A, LOG1EM6);
}

// ---------------------------------------------------------------------------
// Chunk kernel: per (b,h,chunk) block.
//   Y_intra = G @ X  where G[i][j] = exp(la_i - la_j) * dt_j * (C_i . B_j), j<=i
//   T[p][n] = sum_j exp(la_end - la_j) * dt_j * x_j[p] * B_j[n]
//   g_ai[i] = exp(la_i), g_laend = la_end
// Dynamic smem: sX[64][65], sB[64][65], sCt[64][65] (C then G), dt/la/w[64].
// ---------------------------------------------------------------------------
__global__ __launch_bounds__(256) void chunk_kernel(
    const float* __restrict__ xbc, const float* __restrict__ dtb,
    const float* __restrict__ lda, float* __restrict__ yintra,
    float* __restrict__ Tg, float* __restrict__ aig,
    float* __restrict__ laendg)
{
    extern __shared__ float sm[];
    float* sX  = sm;
    float* sB  = sm + 4160;
    float* sCt = sm + 8320;
    float* sdt = sm + 12480;
    float* sla = sdt + 64;
    float* sw  = sla + 64;

    const int bhc = blockIdx.x;
    const int c = bhc & (NCHUNK - 1);
    const int h = (bhc >> 3) % NHEADS;
    const int b = bhc / (NCHUNK * NHEADS);
    const int tid = threadIdx.x;
    const int row0 = b * LL + c * QC;

    // stage X, B, C tiles
#pragma unroll
    for (int idx = tid; idx < 64 * 16; idx += 256) {
        int i = idx >> 4, f = idx & 15;
        const float* rp = xbc + (size_t)(row0 + i) * CONV_DIM;
        float4 xv = *(const float4*)(rp + h * HEADDIM + f * 4);
        float4 bv = *(const float4*)(rp + D_SSM + f * 4);
        float4 cv = *(const float4*)(rp + D_SSM + D_STATE + f * 4);
        float* xr = sX + i * 65 + f * 4;
        xr[0] = xv.x; xr[1] = xv.y; xr[2] = xv.z; xr[3] = xv.w;
        float* br = sB + i * 65 + f * 4;
        br[0] = bv.x; br[1] = bv.y; br[2] = bv.z; br[3] = bv.w;
        float* cr = sCt + i * 65 + f * 4;
        cr[0] = cv.x; cr[1] = cv.y; cr[2] = cv.z; cr[3] = cv.w;
    }
    if (tid < 64) {
        sdt[tid] = dtb[(row0 + tid) * NHEADS + h];
        sla[tid] = lda[(row0 + tid) * NHEADS + h];
    }
    __syncthreads();
    if (tid == 0) {
        float acc = 0.f;
#pragma unroll
        for (int i = 0; i < 64; i++) { acc += sla[i]; sla[i] = acc; }
    }
    __syncthreads();
    if (tid < 64) {
        sw[tid] = expf(sla[63] - sla[tid]) * sdt[tid];
        aig[bhc * QC + tid] = expf(sla[tid]);
        if (tid == 0) laendg[bhc] = sla[63];
    }

    const int ti = tid >> 4, tj = tid & 15;
    const int i0 = ti * 4, j0 = tj * 4;

    // --- GEMM1: CB = C @ B^T, masked/scaled into G (registers) ---
    float acc1[4][4];
#pragma unroll
    for (int a = 0; a < 4; a++)
#pragma unroll
        for (int q = 0; q < 4; q++) acc1[a][q] = 0.f;
#pragma unroll
    for (int n = 0; n < 64; n++) {
        float cv[4], bv[4];
#pragma unroll
        for (int a = 0; a < 4; a++) cv[a] = sCt[(i0 + a) * 65 + n];
#pragma unroll
        for (int q = 0; q < 4; q++) bv[q] = sB[(j0 + q) * 65 + n];
#pragma unroll
        for (int a = 0; a < 4; a++)
#pragma unroll
            for (int q = 0; q < 4; q++)
                acc1[a][q] = fmaf(cv[a], bv[q], acc1[a][q]);
    }
    float gv[4][4];
#pragma unroll
    for (int a = 0; a < 4; a++) {
        int i = i0 + a;
#pragma unroll
        for (int q = 0; q < 4; q++) {
            int j = j0 + q;
            gv[a][q] = (j <= i)
                ? acc1[a][q] * sdt[j] * expf(sla[i] - sla[j]) : 0.f;
        }
    }
    __syncthreads();
#pragma unroll
    for (int a = 0; a < 4; a++)
#pragma unroll
        for (int q = 0; q < 4; q++)
            sCt[(i0 + a) * 65 + j0 + q] = gv[a][q];
    __syncthreads();

    // --- GEMM2: Y_intra = G @ X  (i x p) ---
    {
        float acc2[4][4];
#pragma unroll
        for (int a = 0; a < 4; a++)
#pragma unroll
            for (int q = 0; q < 4; q++) acc2[a][q] = 0.f;
#pragma unroll
        for (int j = 0; j < 64; j++) {
            float g4[4], x4[4];
#pragma unroll
            for (int a = 0; a < 4; a++) g4[a] = sCt[(i0 + a) * 65 + j];
#pragma unroll
            for (int q = 0; q < 4; q++) x4[q] = sX[j * 65 + j0 + q];
#pragma unroll
            for (int a = 0; a < 4; a++)
#pragma unroll
                for (int q = 0; q < 4; q++)
                    acc2[a][q] = fmaf(g4[a], x4[q], acc2[a][q]);
        }
#pragma unroll
        for (int a = 0; a < 4; a++)
#pragma unroll
            for (int q = 0; q < 4; q++)
                yintra[(size_t)(row0 + i0 + a) * D_SSM + h * HEADDIM + j0 + q]
                    = acc2[a][q];
    }

    // --- GEMM3: T[p][n] = sum_j w_j * x_j[p] * B_j[n] ---
    {
        float acc3[4][4];
#pragma unroll
        for (int a = 0; a < 4; a++)
#pragma unroll
            for (int q = 0; q < 4; q++) acc3[a][q] = 0.f;
#pragma unroll
        for (int j = 0; j < 64; j++) {
            float wj = sw[j];
            float x4[4], b4[4];
#pragma unroll
            for (int a = 0; a < 4; a++) x4[a] = sX[j * 65 + i0 + a] * wj;
#pragma unroll
            for (int q = 0; q < 4; q++) b4[q] = sB[j * 65 + j0 + q];
#pragma unroll
            for (int a = 0; a < 4; a++)
#pragma unroll
                for (int q = 0; q < 4; q++)
                    acc3[a][q] = fmaf(x4[a], b4[q], acc3[a][q]);
        }
#pragma unroll
        for (int a = 0; a < 4; a++)
#pragma unroll
            for (int q = 0; q < 4; q++)
                Tg[(size_t)bhc * 4096 + (i0 + a) * 64 + j0 + q] = acc3[a][q];
    }
}

// ---------------------------------------------------------------------------
// Sequential chunk-state combine: 48 blocks (b,h). 8 steps, state in regs.
// Writes state ENTERING chunk c to g_S[bhc], then S = exp(la_end)*S + T_c.
// ---------------------------------------------------------------------------
__global__ __launch_bounds__(256) void combine_kernel(
    const float* __restrict__ Tg, const float* __restrict__ laendg,
    float* __restrict__ Sg)
{
    const int bh = blockIdx.x;
    const int off = threadIdx.x * 16;
    float4 s[4];
#pragma unroll
    for (int k = 0; k < 4; k++) s[k] = make_float4(0.f, 0.f, 0.f, 0.f);

#pragma unroll
    for (int c = 0; c < NCHUNK; c++) {
        int bhc = bh * NCHUNK + c;
        float4* dst = (float4*)(Sg + (size_t)bhc * 4096 + off);
#pragma unroll
        for (int k = 0; k < 4; k++) dst[k] = s[k];
        float ae = expf(laendg[bhc]);
        const float4* tp = (const float4*)(Tg + (size_t)bhc * 4096 + off);
#pragma unroll
        for (int k = 0; k < 4; k++) {
            float4 t = tp[k];
            s[k].x = fmaf(ae, s[k].x, t.x);
            s[k].y = fmaf(ae, s[k].y, t.y);
            s[k].z = fmaf(ae, s[k].z, t.z);
            s[k].w = fmaf(ae, s[k].w, t.w);
        }
    }
}

// ---------------------------------------------------------------------------
// Inter-chunk contribution + skip + gating:
//   y[i][p] = (Y_intra + exp(la_i) * (C_i . S0)[p] + D*x) * silu(z)
// ---------------------------------------------------------------------------
__global__ __launch_bounds__(256) void inter_kernel(
    const float* __restrict__ xbc, const float* __restrict__ Sg,
    const float* __restrict__ aig, const float* __restrict__ zx,
    const float* __restrict__ Dp, float* __restrict__ y)
{
    __shared__ float sC[64 * 65];
    __shared__ float sS[64 * 65];
    __shared__ float sai[64];

    const int bhc = blockIdx.x;
    const int c = bhc & (NCHUNK - 1);
    const int h = (bhc >> 3) % NHEADS;
    const int b = bhc / (NCHUNK * NHEADS);
    const int tid = threadIdx.x;
    const int row0 = b * LL + c * QC;

#pragma unroll
    for (int idx = tid; idx < 64 * 16; idx += 256) {
        int i = idx >> 4, f = idx & 15;
        const float* rp = xbc + (size_t)(row0 + i) * CONV_DIM;
        float4 cv = *(const float4*)(rp + D_SSM + D_STATE + f * 4);
        float* cr = sC + i * 65 + f * 4;
        cr[0] = cv.x; cr[1] = cv.y; cr[2] = cv.z; cr[3] = cv.w;
        float4 sv = *(const float4*)(Sg + (size_t)bhc * 4096 + i * 64 + f * 4);
        float* sr = sS + i * 65 + f * 4;
        sr[0] = sv.x; sr[1] = sv.y; sr[2] = sv.z; sr[3] = sv.w;
    }
    if (tid < 64) sai[tid] = aig[bhc * QC + tid];
    __syncthreads();

    const int ti = tid >> 4, tj = tid & 15;
    const int i0 = ti * 4, p0 = tj * 4;

    float acc[4][4];
#pragma unroll
    for (int a = 0; a < 4; a++)
#pragma unroll
        for (int q = 0; q < 4; q++) acc[a][q] = 0.f;
#pragma unroll
    for (int n = 0; n < 64; n++) {
        float cv[4], sv[4];
#pragma unroll
        for (int a = 0; a < 4; a++) cv[a] = sC[(i0 + a) * 65 + n];
#pragma unroll
        for (int q = 0; q < 4; q++) sv[q] = sS[(p0 + q) * 65 + n];
#pragma unroll
        for (int a = 0; a < 4; a++)
#pragma unroll
            for (int q = 0; q < 4; q++)
                acc[a][q] = fmaf(cv[a], sv[q], acc[a][q]);
    }

    const float Dv = Dp[h];
#pragma unroll
    for (int a = 0; a < 4; a++) {
        int i = i0 + a;
        size_t r = row0 + i;
#pragma unroll
        for (int q = 0; q < 4; q++) {
            int p = p0 + q;
            float xv = xbc[r * CONV_DIM + h * HEADDIM + p];
            float zv = zx[r * D_IN_PROJ + h * HEADDIM + p];
            size_t yi = r * D_SSM + h * HEADDIM + p;
            float yv = y[yi] + sai[i] * acc[a][q] + Dv * xv;
            float sig = 1.f / (1.f + expf(-zv));
            y[yi] = yv * zv * sig;
        }
    }
}

// ---------------------------------------------------------------------------
// Launch
// ---------------------------------------------------------------------------
extern "C" void kernel_launch(void* const* d_in, const int* in_sizes, int n_in,
                              void* d_out, int out_size)
{
    const float* u       = (const float*)d_in[0];
    const float* W_in    = (const float*)d_in[1];
    const float* conv_w  = (const float*)d_in[2];
    const float* conv_b  = (const float*)d_in[3];
    const float* dt_bias = (const float*)d_in[4];
    const float* A_log   = (const float*)d_in[5];
    const float* D_param = (const float*)d_in[6];
    const float* W_out   = (const float*)d_in[7];
    float* out = (float*)d_out;

    float *zx, *xbc, *dt, *ldA, *y, *Tg, *Sg, *aig, *laendg;
    cudaGetSymbolAddress((void**)&zx,     g_zxbcdt);
    cudaGetSymbolAddress((void**)&xbc,    g_xbc);
    cudaGetSymbolAddress((void**)&dt,     g_dt);
    cudaGetSymbolAddress((void**)&ldA,    g_ldA);
    cudaGetSymbolAddress((void**)&y,      g_y);
    cudaGetSymbolAddress((void**)&Tg,     g_T);
    cudaGetSymbolAddress((void**)&Sg,     g_S);
    cudaGetSymbolAddress((void**)&aig,    g_ai);
    cudaGetSymbolAddress((void**)&laendg, g_laend);

    static bool attr_done = false;
    if (!attr_done) {
        cudaFuncSetAttribute(chunk_kernel,
                             cudaFuncAttributeMaxDynamicSharedMemorySize,
                             51200);
        attr_done = true;
    }

    // 1) in_proj
    {
        dim3 grid((D_IN_PROJ + 63) / 64, BL / 128);
        sgemm_tn<128, 64, 16, 8, 4><<<grid, 256>>>(u, W_in, zx, BL, D_IN_PROJ, D_MODEL);
    }
    // 2) conv + silu
    {
        int cnt = BL * CONV_DIM;
        conv_silu_kernel<<<(cnt + 255) / 256, 256>>>(zx, conv_w, conv_b, xbc);
    }
    // 3) dt / log(dA)
    {
        int cnt = BL * NHEADS;
        dtda_kernel<<<(cnt + 255) / 256, 256>>>(zx, dt_bias, A_log, dt, ldA);
    }
    // 4) chunked scan
    chunk_kernel<<<NBHC, 256, 51200>>>(xbc, dt, ldA, y, Tg, aig, laendg);
    combine_kernel<<<BB * NHEADS, 256>>>(Tg, laendg, Sg);
    inter_kernel<<<NBHC, 256>>>(xbc, Sg, aig, zx, D_param, y);

    // 5) out_proj
    {
        dim3 grid(D_MODEL / 64, BL / 64);
        sgemm_tn<64, 64, 16, 4, 4><<<grid, 256>>>(y, W_out, out, BL, D_MODEL, D_SSM);
    }
}

// round 3
// speedup vs baseline: 3.0743x; 1.3621x over previous
#include <cuda_runtime.h>
#include <cuda_bf16.h>
#include <math.h>
#include <stdint.h>

// ---------------------------------------------------------------------------
// Problem dimensions (compile-time)
// ---------------------------------------------------------------------------
#define D_MODEL   768
#define D_STATE   64
#define D_CONV    4
#define D_SSM     1536
#define HEADDIM   64
#define NHEADS    24
#define CONV_DIM  1664
#define D_IN_PROJ 3224
#define BB        2
#define LL        512
#define BL        (BB*LL)
#define QC        64
#define NCHUNK    (LL/QC)
#define NBHC      (BB*NHEADS*NCHUNK)

#define DT_OFF    (D_SSM + CONV_DIM)
#define LOG1EM6   (-13.815510558f)

// ---------------------------------------------------------------------------
// Scratch (static device globals)
// ---------------------------------------------------------------------------
__device__ float g_zxbcdt[BL * D_IN_PROJ];
__device__ float g_xbc[BL * CONV_DIM];
__device__ float g_dt[BL * NHEADS];
__device__ float g_ldA[BL * NHEADS];
__device__ float g_y[BL * D_SSM];
__device__ float g_T[NBHC * HEADDIM * D_STATE];
__device__ float g_S[NBHC * HEADDIM * D_STATE];
__device__ float g_ai[NBHC * QC];
__device__ float g_laend[NBHC];

// ---------------------------------------------------------------------------
// TF32 helpers
// ---------------------------------------------------------------------------
__device__ __forceinline__ uint32_t f2tf(float x) {
    uint32_t r;
    asm("cvt.rna.tf32.f32 %0, %1;" : "=r"(r) : "f"(x));
    return r;
}

__device__ __forceinline__ void mma8(float* d, const uint32_t* a, const uint32_t* b) {
    asm volatile(
        "mma.sync.aligned.m16n8k8.row.col.f32.tf32.tf32.f32 "
        "{%0,%1,%2,%3},{%4,%5,%6,%7},{%8,%9},{%0,%1,%2,%3};"
        : "+f"(d[0]), "+f"(d[1]), "+f"(d[2]), "+f"(d[3])
        : "r"(a[0]), "r"(a[1]), "r"(a[2]), "r"(a[3]), "r"(b[0]), "r"(b[1]));
}

__device__ __forceinline__ void cp16(uint32_t dst, const void* src, bool pred) {
    int bytes = pred ? 16 : 0;
    asm volatile("cp.async.cg.shared.global [%0], [%1], 16, %2;\n"
                 :: "r"(dst), "l"(src), "r"(bytes));
}

// ---------------------------------------------------------------------------
// TF32 MMA GEMM:  C[m, n] = sum_k A[m,k] * W[n,k]
// Block tile BM x BN, BK=32, 256 threads, warp grid 2(m) x 4(n).
// Per-block-column precision: 1x tf32 for n0 < x3col0, tf32x3 otherwise.
// Assumes M % BM == 0, K % 32 == 0; W rows guarded vs Nw; stores guarded vs Nv.
// ---------------------------------------------------------------------------
template<int BM, int BN>
__global__ __launch_bounds__(256) void mma_gemm(
    const float* __restrict__ A, const float* __restrict__ W,
    float* __restrict__ Cout, int Nw, int Nv, int Nstride, int K, int x3col0)
{
    constexpr int MT = BM / 32;      // m16 tiles per warp (BM/2 /16)
    constexpr int NT = BN / 32;      // n8 tiles per warp  (BN/4 /8)
    constexpr int SK = 36;           // padded smem row stride (floats)

    extern __shared__ float sm_f[];
    float* smA = sm_f;                       // [2][BM][36]
    float* smW = sm_f + 2 * BM * SK;         // [2][BN][36]

    const int tid  = threadIdx.x;
    const int lane = tid & 31;
    const int warp = tid >> 5;
    const int wm0  = (warp & 1) * (BM / 2);
    const int wn0  = (warp >> 1) * (BN / 4);
    const int m0   = blockIdx.y * BM;
    const int n0   = blockIdx.x * BN;
    const bool x3  = (n0 >= x3col0);
    const int gr   = lane >> 2;
    const int lk   = lane & 3;

    uint32_t smA_u = (uint32_t)__cvta_generic_to_shared(smA);
    uint32_t smW_u = (uint32_t)__cvta_generic_to_shared(smW);

    float acc[MT][NT][4];
#pragma unroll
    for (int mi = 0; mi < MT; mi++)
#pragma unroll
        for (int ni = 0; ni < NT; ni++)
#pragma unroll
            for (int r = 0; r < 4; r++) acc[mi][ni][r] = 0.f;

    auto load_stage = [&](int s, int kt) {
#pragma unroll
        for (int i = 0; i < BM * 8 / 256; i++) {
            int idx = tid + i * 256;
            int row = idx >> 3, c4 = idx & 7;
            cp16(smA_u + (uint32_t)(s * BM * SK + row * SK + c4 * 4) * 4,
                 A + (size_t)(m0 + row) * K + kt + c4 * 4, true);
        }
#pragma unroll
        for (int i = 0; i < BN * 8 / 256; i++) {
            int idx = tid + i * 256;
            int row = idx >> 3, c4 = idx & 7;
            cp16(smW_u + (uint32_t)(s * BN * SK + row * SK + c4 * 4) * 4,
                 W + (size_t)(n0 + row) * K + kt + c4 * 4, (n0 + row) < Nw);
        }
        asm volatile("cp.async.commit_group;");
    };

    const int nk = K / 32;
    load_stage(0, 0);

    for (int kt = 0; kt < nk; kt++) {
        if (kt + 1 < nk) {
            load_stage((kt + 1) & 1, (kt + 1) * 32);
            asm volatile("cp.async.wait_group 1;");
        } else {
            asm volatile("cp.async.wait_group 0;");
        }
        __syncthreads();

        const float* sA = smA + (kt & 1) * BM * SK;
        const float* sW = smW + (kt & 1) * BN * SK;

#pragma unroll
        for (int k8 = 0; k8 < 4; k8++) {
            const int kb = k8 * 8 + lk;
            float ar[MT][4];
#pragma unroll
            for (int mi = 0; mi < MT; mi++) {
                int r = wm0 + mi * 16 + gr;
                ar[mi][0] = sA[r * SK + kb];
                ar[mi][1] = sA[(r + 8) * SK + kb];
                ar[mi][2] = sA[r * SK + kb + 4];
                ar[mi][3] = sA[(r + 8) * SK + kb + 4];
            }
            float brr[NT][2];
#pragma unroll
            for (int ni = 0; ni < NT; ni++) {
                int n = wn0 + ni * 8 + gr;
                brr[ni][0] = sW[n * SK + kb];
                brr[ni][1] = sW[n * SK + kb + 4];
            }

            if (!x3) {
                uint32_t ua[MT][4], ub[NT][2];
#pragma unroll
                for (int mi = 0; mi < MT; mi++)
#pragma unroll
                    for (int r = 0; r < 4; r++) ua[mi][r] = f2tf(ar[mi][r]);
#pragma unroll
                for (int ni = 0; ni < NT; ni++) {
                    ub[ni][0] = f2tf(brr[ni][0]);
                    ub[ni][1] = f2tf(brr[ni][1]);
                }
#pragma unroll
                for (int mi = 0; mi < MT; mi++)
#pragma unroll
                    for (int ni = 0; ni < NT; ni++)
                        mma8(acc[mi][ni], ua[mi], ub[ni]);
            } else {
                uint32_t ubh[NT][2], ubl[NT][2];
#pragma unroll
                for (int ni = 0; ni < NT; ni++) {
#pragma unroll
                    for (int j = 0; j < 2; j++) {
                        uint32_t h = f2tf(brr[ni][j]);
                        ubh[ni][j] = h;
                        ubl[ni][j] = f2tf(brr[ni][j] - __uint_as_float(h));
                    }
                }
#pragma unroll
                for (int mi = 0; mi < MT; mi++) {
                    uint32_t uah[4], ual[4];
#pragma unroll
                    for (int r = 0; r < 4; r++) {
                        uint32_t h = f2tf(ar[mi][r]);
                        uah[r] = h;
                        ual[r] = f2tf(ar[mi][r] - __uint_as_float(h));
                    }
#pragma unroll
                    for (int ni = 0; ni < NT; ni++) {
                        mma8(acc[mi][ni], ual, ubh[ni]);
                        mma8(acc[mi][ni], uah, ubl[ni]);
                        mma8(acc[mi][ni], uah, ubh[ni]);
                    }
                }
            }
        }
        __syncthreads();
    }

    // epilogue
#pragma unroll
    for (int mi = 0; mi < MT; mi++) {
        int row = m0 + wm0 + mi * 16 + gr;
#pragma unroll
        for (int ni = 0; ni < NT; ni++) {
            int col = n0 + wn0 + ni * 8 + lk * 2;
            if (col < Nv) {
                *(float2*)(Cout + (size_t)row * Nstride + col) =
                    make_float2(acc[mi][ni][0], acc[mi][ni][1]);
                *(float2*)(Cout + (size_t)(row + 8) * Nstride + col) =
                    make_float2(acc[mi][ni][2], acc[mi][ni][3]);
            }
        }
    }
}

// ---------------------------------------------------------------------------
// Depthwise causal conv (width 4) + bias + SiLU
// ---------------------------------------------------------------------------
__global__ void conv_silu_kernel(const float* __restrict__ zx,
                                 const float* __restrict__ cw,
                                 const float* __restrict__ cb,
                                 float* __restrict__ out)
{
    int idx = blockIdx.x * blockDim.x + threadIdx.x;
    if (idx >= BL * CONV_DIM) return;
    int c  = idx % CONV_DIM;
    int bl = idx / CONV_DIM;
    int l  = bl % LL;
    int b  = bl / LL;

    float sum = cb[c];
#pragma unroll
    for (int j = 0; j < D_CONV; j++) {
        int t = l + j - (D_CONV - 1);
        if (t >= 0)
            sum = fmaf(zx[(size_t)(b * LL + t) * D_IN_PROJ + D_SSM + c],
                       cw[c * D_CONV + j], sum);
    }
    float sig = 1.f / (1.f + expf(-sum));
    out[idx] = sum * sig;
}

// ---------------------------------------------------------------------------
// dt / log(dA)
// ---------------------------------------------------------------------------
__global__ void dtda_kernel(const float* __restrict__ zx,
                            const float* __restrict__ dt_bias,
                            const float* __restrict__ A_log,
                            float* __restrict__ dt_out,
                            float* __restrict__ ldA_out)
{
    int idx = blockIdx.x * blockDim.x + threadIdx.x;
    if (idx >= BL * NHEADS) return;
    int h  = idx % NHEADS;
    int bl = idx / NHEADS;

    float raw = zx[(size_t)bl * D_IN_PROJ + DT_OFF + h] + dt_bias[h];
    float sp = fmaxf(raw, 0.f) + log1pf(expf(-fabsf(raw)));
    float dt = fminf(fmaxf(sp, 1e-6f), 1000.f);
    float A  = -expf(A_log[h]);
    dt_out[idx]  = dt;
    ldA_out[idx] = fmaxf(dt * A, LOG1EM6);
}

// ---------------------------------------------------------------------------
// Chunk kernel (intra-chunk GEMMs + chunk summary)
// ---------------------------------------------------------------------------
__global__ __launch_bounds__(256) void chunk_kernel(
    const float* __restrict__ xbc, const float* __restrict__ dtb,
    const float* __restrict__ lda, float* __restrict__ yintra,
    float* __restrict__ Tg, float* __restrict__ aig,
    float* __restrict__ laendg)
{
    extern __shared__ float sm[];
    float* sX  = sm;
    float* sB  = sm + 4160;
    float* sCt = sm + 8320;
    float* sdt = sm + 12480;
    float* sla = sdt + 64;
    float* sw  = sla + 64;

    const int bhc = blockIdx.x;
    const int c = bhc & (NCHUNK - 1);
    const int h = (bhc >> 3) % NHEADS;
    const int b = bhc / (NCHUNK * NHEADS);
    const int tid = threadIdx.x;
    const int row0 = b * LL + c * QC;

#pragma unroll
    for (int idx = tid; idx < 64 * 16; idx += 256) {
        int i = idx >> 4, f = idx & 15;
        const float* rp = xbc + (size_t)(row0 + i) * CONV_DIM;
        float4 xv = *(const float4*)(rp + h * HEADDIM + f * 4);
        float4 bv = *(const float4*)(rp + D_SSM + f * 4);
        float4 cv = *(const float4*)(rp + D_SSM + D_STATE + f * 4);
        float* xr = sX + i * 65 + f * 4;
        xr[0] = xv.x; xr[1] = xv.y; xr[2] = xv.z; xr[3] = xv.w;
        float* br = sB + i * 65 + f * 4;
        br[0] = bv.x; br[1] = bv.y; br[2] = bv.z; br[3] = bv.w;
        float* cr = sCt + i * 65 + f * 4;
        cr[0] = cv.x; cr[1] = cv.y; cr[2] = cv.z; cr[3] = cv.w;
    }
    if (tid < 64) {
        sdt[tid] = dtb[(row0 + tid) * NHEADS + h];
        sla[tid] = lda[(row0 + tid) * NHEADS + h];
    }
    __syncthreads();
    if (tid == 0) {
        float acc = 0.f;
#pragma unroll
        for (int i = 0; i < 64; i++) { acc += sla[i]; sla[i] = acc; }
    }
    __syncthreads();
    if (tid < 64) {
        sw[tid] = expf(sla[63] - sla[tid]) * sdt[tid];
        aig[bhc * QC + tid] = expf(sla[tid]);
        if (tid == 0) laendg[bhc] = sla[63];
    }

    const int ti = tid >> 4, tj = tid & 15;
    const int i0 = ti * 4, j0 = tj * 4;

    float acc1[4][4];
#pragma unroll
    for (int a = 0; a < 4; a++)
#pragma unroll
        for (int q = 0; q < 4; q++) acc1[a][q] = 0.f;
#pragma unroll
    for (int n = 0; n < 64; n++) {
        float cv[4], bv[4];
#pragma unroll
        for (int a = 0; a < 4; a++) cv[a] = sCt[(i0 + a) * 65 + n];
#pragma unroll
        for (int q = 0; q < 4; q++) bv[q] = sB[(j0 + q) * 65 + n];
#pragma unroll
        for (int a = 0; a < 4; a++)
#pragma unroll
            for (int q = 0; q < 4; q++)
                acc1[a][q] = fmaf(cv[a], bv[q], acc1[a][q]);
    }
    float gv[4][4];
#pragma unroll
    for (int a = 0; a < 4; a++) {
        int i = i0 + a;
#pragma unroll
        for (int q = 0; q < 4; q++) {
            int j = j0 + q;
            gv[a][q] = (j <= i)
                ? acc1[a][q] * sdt[j] * expf(sla[i] - sla[j]) : 0.f;
        }
    }
    __syncthreads();
#pragma unroll
    for (int a = 0; a < 4; a++)
#pragma unroll
        for (int q = 0; q < 4; q++)
            sCt[(i0 + a) * 65 + j0 + q] = gv[a][q];
    __syncthreads();

    {
        float acc2[4][4];
#pragma unroll
        for (int a = 0; a < 4; a++)
#pragma unroll
            for (int q = 0; q < 4; q++) acc2[a][q] = 0.f;
#pragma unroll
        for (int j = 0; j < 64; j++) {
            float g4[4], x4[4];
#pragma unroll
            for (int a = 0; a < 4; a++) g4[a] = sCt[(i0 + a) * 65 + j];
#pragma unroll
            for (int q = 0; q < 4; q++) x4[q] = sX[j * 65 + j0 + q];
#pragma unroll
            for (int a = 0; a < 4; a++)
#pragma unroll
                for (int q = 0; q < 4; q++)
                    acc2[a][q] = fmaf(g4[a], x4[q], acc2[a][q]);
        }
#pragma unroll
        for (int a = 0; a < 4; a++)
#pragma unroll
            for (int q = 0; q < 4; q++)
                yintra[(size_t)(row0 + i0 + a) * D_SSM + h * HEADDIM + j0 + q]
                    = acc2[a][q];
    }

    {
        float acc3[4][4];
#pragma unroll
        for (int a = 0; a < 4; a++)
#pragma unroll
            for (int q = 0; q < 4; q++) acc3[a][q] = 0.f;
#pragma unroll
        for (int j = 0; j < 64; j++) {
            float wj = sw[j];
            float x4[4], b4[4];
#pragma unroll
            for (int a = 0; a < 4; a++) x4[a] = sX[j * 65 + i0 + a] * wj;
#pragma unroll
            for (int q = 0; q < 4; q++) b4[q] = sB[j * 65 + j0 + q];
#pragma unroll
            for (int a = 0; a < 4; a++)
#pragma unroll
                for (int q = 0; q < 4; q++)
                    acc3[a][q] = fmaf(x4[a], b4[q], acc3[a][q]);
        }
#pragma unroll
        for (int a = 0; a < 4; a++)
#pragma unroll
            for (int q = 0; q < 4; q++)
                Tg[(size_t)bhc * 4096 + (i0 + a) * 64 + j0 + q] = acc3[a][q];
    }
}

// ---------------------------------------------------------------------------
// Sequential chunk-state combine
// ---------------------------------------------------------------------------
__global__ __launch_bounds__(256) void combine_kernel(
    const float* __restrict__ Tg, const float* __restrict__ laendg,
    float* __restrict__ Sg)
{
    const int bh = blockIdx.x;
    const int off = threadIdx.x * 16;
    float4 s[4];
#pragma unroll
    for (int k = 0; k < 4; k++) s[k] = make_float4(0.f, 0.f, 0.f, 0.f);

#pragma unroll
    for (int c = 0; c < NCHUNK; c++) {
        int bhc = bh * NCHUNK + c;
        float4* dst = (float4*)(Sg + (size_t)bhc * 4096 + off);
#pragma unroll
        for (int k = 0; k < 4; k++) dst[k] = s[k];
        float ae = expf(laendg[bhc]);
        const float4* tp = (const float4*)(Tg + (size_t)bhc * 4096 + off);
#pragma unroll
        for (int k = 0; k < 4; k++) {
            float4 t = tp[k];
            s[k].x = fmaf(ae, s[k].x, t.x);
            s[k].y = fmaf(ae, s[k].y, t.y);
            s[k].z = fmaf(ae, s[k].z, t.z);
            s[k].w = fmaf(ae, s[k].w, t.w);
        }
    }
}

// ---------------------------------------------------------------------------
// Inter-chunk contribution + skip + gating
// ---------------------------------------------------------------------------
__global__ __launch_bounds__(256) void inter_kernel(
    const float* __restrict__ xbc, const float* __restrict__ Sg,
    const float* __restrict__ aig, const float* __restrict__ zx,
    const float* __restrict__ Dp, float* __restrict__ y)
{
    __shared__ float sC[64 * 65];
    __shared__ float sS[64 * 65];
    __shared__ float sai[64];

    const int bhc = blockIdx.x;
    const int c = bhc & (NCHUNK - 1);
    const int h = (bhc >> 3) % NHEADS;
    const int b = bhc / (NCHUNK * NHEADS);
    const int tid = threadIdx.x;
    const int row0 = b * LL + c * QC;

#pragma unroll
    for (int idx = tid; idx < 64 * 16; idx += 256) {
        int i = idx >> 4, f = idx & 15;
        const float* rp = xbc + (size_t)(row0 + i) * CONV_DIM;
        float4 cv = *(const float4*)(rp + D_SSM + D_STATE + f * 4);
        float* cr = sC + i * 65 + f * 4;
        cr[0] = cv.x; cr[1] = cv.y; cr[2] = cv.z; cr[3] = cv.w;
        float4 sv = *(const float4*)(Sg + (size_t)bhc * 4096 + i * 64 + f * 4);
        float* sr = sS + i * 65 + f * 4;
        sr[0] = sv.x; sr[1] = sv.y; sr[2] = sv.z; sr[3] = sv.w;
    }
    if (tid < 64) sai[tid] = aig[bhc * QC + tid];
    __syncthreads();

    const int ti = tid >> 4, tj = tid & 15;
    const int i0 = ti * 4, p0 = tj * 4;

    float acc[4][4];
#pragma unroll
    for (int a = 0; a < 4; a++)
#pragma unroll
        for (int q = 0; q < 4; q++) acc[a][q] = 0.f;
#pragma unroll
    for (int n = 0; n < 64; n++) {
        float cv[4], sv[4];
#pragma unroll
        for (int a = 0; a < 4; a++) cv[a] = sC[(i0 + a) * 65 + n];
#pragma unroll
        for (int q = 0; q < 4; q++) sv[q] = sS[(p0 + q) * 65 + n];
#pragma unroll
        for (int a = 0; a < 4; a++)
#pragma unroll
            for (int q = 0; q < 4; q++)
                acc[a][q] = fmaf(cv[a], sv[q], acc[a][q]);
    }

    const float Dv = Dp[h];
#pragma unroll
    for (int a = 0; a < 4; a++) {
        int i = i0 + a;
        size_t r = row0 + i;
#pragma unroll
        for (int q = 0; q < 4; q++) {
            int p = p0 + q;
            float xv = xbc[r * CONV_DIM + h * HEADDIM + p];
            float zv = zx[r * D_IN_PROJ + h * HEADDIM + p];
            size_t yi = r * D_SSM + h * HEADDIM + p;
            float yv = y[yi] + sai[i] * acc[a][q] + Dv * xv;
            float sig = 1.f / (1.f + expf(-zv));
            y[yi] = yv * zv * sig;
        }
    }
}

// ---------------------------------------------------------------------------
// Launch
// ---------------------------------------------------------------------------
extern "C" void kernel_launch(void* const* d_in, const int* in_sizes, int n_in,
                              void* d_out, int out_size)
{
    const float* u       = (const float*)d_in[0];
    const float* W_in    = (const float*)d_in[1];
    const float* conv_w  = (const float*)d_in[2];
    const float* conv_b  = (const float*)d_in[3];
    const float* dt_bias = (const float*)d_in[4];
    const float* A_log   = (const float*)d_in[5];
    const float* D_param = (const float*)d_in[6];
    const float* W_out   = (const float*)d_in[7];
    float* out = (float*)d_out;

    float *zx, *xbc, *dt, *ldA, *y, *Tg, *Sg, *aig, *laendg;
    cudaGetSymbolAddress((void**)&zx,     g_zxbcdt);
    cudaGetSymbolAddress((void**)&xbc,    g_xbc);
    cudaGetSymbolAddress((void**)&dt,     g_dt);
    cudaGetSymbolAddress((void**)&ldA,    g_ldA);
    cudaGetSymbolAddress((void**)&y,      g_y);
    cudaGetSymbolAddress((void**)&Tg,     g_T);
    cudaGetSymbolAddress((void**)&Sg,     g_S);
    cudaGetSymbolAddress((void**)&aig,    g_ai);
    cudaGetSymbolAddress((void**)&laendg, g_laend);

    static bool attr_done = false;
    if (!attr_done) {
        cudaFuncSetAttribute(chunk_kernel,
                             cudaFuncAttributeMaxDynamicSharedMemorySize, 51200);
        cudaFuncSetAttribute(mma_gemm<128, 128>,
                             cudaFuncAttributeMaxDynamicSharedMemorySize, 73728);
        cudaFuncSetAttribute(mma_gemm<64, 64>,
                             cudaFuncAttributeMaxDynamicSharedMemorySize, 36864);
        attr_done = true;
    }

    // 1) in_proj: cols [0,1536) 1x tf32, cols [1536,3328) tf32x3 (pad guarded)
    {
        dim3 grid(26, BL / 128);
        mma_gemm<128, 128><<<grid, 256, 73728>>>(
            u, W_in, zx, D_IN_PROJ, D_IN_PROJ, D_IN_PROJ, D_MODEL, 1536);
    }
    // 2) conv + silu
    {
        int cnt = BL * CONV_DIM;
        conv_silu_kernel<<<(cnt + 255) / 256, 256>>>(zx, conv_w, conv_b, xbc);
    }
    // 3) dt / log(dA)
    {
        int cnt = BL * NHEADS;
        dtda_kernel<<<(cnt + 255) / 256, 256>>>(zx, dt_bias, A_log, dt, ldA);
    }
    // 4) chunked scan
    chunk_kernel<<<NBHC, 256, 51200>>>(xbc, dt, ldA, y, Tg, aig, laendg);
    combine_kernel<<<BB * NHEADS, 256>>>(Tg, laendg, Sg);
    inter_kernel<<<NBHC, 256>>>(xbc, Sg, aig, zx, D_param, y);

    // 5) out_proj: 1x tf32
    {
        dim3 grid(D_MODEL / 64, BL / 64);
        mma_gemm<64, 64><<<grid, 256, 36864>>>(
            y, W_out, out, D_MODEL, D_MODEL, D_MODEL, D_SSM, 1 << 30);
    }
}

// round 4
// speedup vs baseline: 3.3384x; 1.0859x over previous
#include <cuda_runtime.h>
#include <cuda_bf16.h>
#include <math.h>
#include <stdint.h>

// ---------------------------------------------------------------------------
// Problem dimensions (compile-time)
// ---------------------------------------------------------------------------
#define D_MODEL   768
#define D_STATE   64
#define D_CONV    4
#define D_SSM     1536
#define HEADDIM   64
#define NHEADS    24
#define CONV_DIM  1664
#define D_IN_PROJ 3224
#define BB        2
#define LL        512
#define BL        (BB*LL)
#define QC        64
#define NCHUNK    (LL/QC)
#define NBHC      (BB*NHEADS*NCHUNK)

#define DT_OFF    (D_SSM + CONV_DIM)
#define LOG1EM6   (-13.815510558f)

// ---------------------------------------------------------------------------
// Scratch (static device globals)
// ---------------------------------------------------------------------------
__device__ float g_zxbcdt[BL * D_IN_PROJ];
__device__ float g_xbc[BL * CONV_DIM];
__device__ float g_dt[BL * NHEADS];
__device__ float g_ldA[BL * NHEADS];
__device__ float g_y[BL * D_SSM];
__device__ float g_T[NBHC * HEADDIM * D_STATE];
__device__ float g_S[NBHC * HEADDIM * D_STATE];
__device__ float g_ai[NBHC * QC];
__device__ float g_laend[NBHC];

// ---------------------------------------------------------------------------
// TF32 helpers
// ---------------------------------------------------------------------------
__device__ __forceinline__ uint32_t f2tf(float x) {
    uint32_t r;
    asm("cvt.rna.tf32.f32 %0, %1;" : "=r"(r) : "f"(x));
    return r;
}

__device__ __forceinline__ void mma8(float* d, const uint32_t* a, const uint32_t* b) {
    asm volatile(
        "mma.sync.aligned.m16n8k8.row.col.f32.tf32.tf32.f32 "
        "{%0,%1,%2,%3},{%4,%5,%6,%7},{%8,%9},{%0,%1,%2,%3};"
        : "+f"(d[0]), "+f"(d[1]), "+f"(d[2]), "+f"(d[3])
        : "r"(a[0]), "r"(a[1]), "r"(a[2]), "r"(a[3]), "r"(b[0]), "r"(b[1]));
}

__device__ __forceinline__ void cp16(uint32_t dst, const void* src, bool pred) {
    int bytes = pred ? 16 : 0;
    asm volatile("cp.async.cg.shared.global [%0], [%1], 16, %2;\n"
                 :: "r"(dst), "l"(src), "r"(bytes));
}

// ---------------------------------------------------------------------------
// TF32 MMA GEMM:  C[m, n] = sum_k A[m,k] * W[n,k]
// Block tile BM x BN, BK=32, 256 threads, warp grid 2(m) x 4(n).
// Per-block-column precision: 1x tf32 for n0 < x3col0, tf32x3 otherwise.
// ---------------------------------------------------------------------------
template<int BM, int BN>
__global__ __launch_bounds__(256) void mma_gemm(
    const float* __restrict__ A, const float* __restrict__ W,
    float* __restrict__ Cout, int Nw, int Nv, int Nstride, int K, int x3col0)
{
    constexpr int MT = BM / 32;
    constexpr int NT = BN / 32;
    constexpr int SK = 36;

    extern __shared__ float sm_f[];
    float* smA = sm_f;
    float* smW = sm_f + 2 * BM * SK;

    const int tid  = threadIdx.x;
    const int lane = tid & 31;
    const int warp = tid >> 5;
    const int wm0  = (warp & 1) * (BM / 2);
    const int wn0  = (warp >> 1) * (BN / 4);
    const int m0   = blockIdx.y * BM;
    const int n0   = blockIdx.x * BN;
    const bool x3  = (n0 >= x3col0);
    const int gr   = lane >> 2;
    const int lk   = lane & 3;

    uint32_t smA_u = (uint32_t)__cvta_generic_to_shared(smA);
    uint32_t smW_u = (uint32_t)__cvta_generic_to_shared(smW);

    float acc[MT][NT][4];
#pragma unroll
    for (int mi = 0; mi < MT; mi++)
#pragma unroll
        for (int ni = 0; ni < NT; ni++)
#pragma unroll
            for (int r = 0; r < 4; r++) acc[mi][ni][r] = 0.f;

    auto load_stage = [&](int s, int kt) {
#pragma unroll
        for (int i = 0; i < BM * 8 / 256; i++) {
            int idx = tid + i * 256;
            int row = idx >> 3, c4 = idx & 7;
            cp16(smA_u + (uint32_t)(s * BM * SK + row * SK + c4 * 4) * 4,
                 A + (size_t)(m0 + row) * K + kt + c4 * 4, true);
        }
#pragma unroll
        for (int i = 0; i < BN * 8 / 256; i++) {
            int idx = tid + i * 256;
            int row = idx >> 3, c4 = idx & 7;
            cp16(smW_u + (uint32_t)(s * BN * SK + row * SK + c4 * 4) * 4,
                 W + (size_t)(n0 + row) * K + kt + c4 * 4, (n0 + row) < Nw);
        }
        asm volatile("cp.async.commit_group;");
    };

    const int nk = K / 32;
    load_stage(0, 0);

    for (int kt = 0; kt < nk; kt++) {
        if (kt + 1 < nk) {
            load_stage((kt + 1) & 1, (kt + 1) * 32);
            asm volatile("cp.async.wait_group 1;");
        } else {
            asm volatile("cp.async.wait_group 0;");
        }
        __syncthreads();

        const float* sA = smA + (kt & 1) * BM * SK;
        const float* sW = smW + (kt & 1) * BN * SK;

#pragma unroll
        for (int k8 = 0; k8 < 4; k8++) {
            const int kb = k8 * 8 + lk;
            float ar[MT][4];
#pragma unroll
            for (int mi = 0; mi < MT; mi++) {
                int r = wm0 + mi * 16 + gr;
                ar[mi][0] = sA[r * SK + kb];
                ar[mi][1] = sA[(r + 8) * SK + kb];
                ar[mi][2] = sA[r * SK + kb + 4];
                ar[mi][3] = sA[(r + 8) * SK + kb + 4];
            }
            float brr[NT][2];
#pragma unroll
            for (int ni = 0; ni < NT; ni++) {
                int n = wn0 + ni * 8 + gr;
                brr[ni][0] = sW[n * SK + kb];
                brr[ni][1] = sW[n * SK + kb + 4];
            }

            if (!x3) {
                uint32_t ua[MT][4], ub[NT][2];
#pragma unroll
                for (int mi = 0; mi < MT; mi++)
#pragma unroll
                    for (int r = 0; r < 4; r++) ua[mi][r] = f2tf(ar[mi][r]);
#pragma unroll
                for (int ni = 0; ni < NT; ni++) {
                    ub[ni][0] = f2tf(brr[ni][0]);
                    ub[ni][1] = f2tf(brr[ni][1]);
                }
#pragma unroll
                for (int mi = 0; mi < MT; mi++)
#pragma unroll
                    for (int ni = 0; ni < NT; ni++)
                        mma8(acc[mi][ni], ua[mi], ub[ni]);
            } else {
                uint32_t ubh[NT][2], ubl[NT][2];
#pragma unroll
                for (int ni = 0; ni < NT; ni++) {
#pragma unroll
                    for (int j = 0; j < 2; j++) {
                        uint32_t hh = f2tf(brr[ni][j]);
                        ubh[ni][j] = hh;
                        ubl[ni][j] = f2tf(brr[ni][j] - __uint_as_float(hh));
                    }
                }
#pragma unroll
                for (int mi = 0; mi < MT; mi++) {
                    uint32_t uah[4], ual[4];
#pragma unroll
                    for (int r = 0; r < 4; r++) {
                        uint32_t hh = f2tf(ar[mi][r]);
                        uah[r] = hh;
                        ual[r] = f2tf(ar[mi][r] - __uint_as_float(hh));
                    }
#pragma unroll
                    for (int ni = 0; ni < NT; ni++) {
                        mma8(acc[mi][ni], ual, ubh[ni]);
                        mma8(acc[mi][ni], uah, ubl[ni]);
                        mma8(acc[mi][ni], uah, ubh[ni]);
                    }
                }
            }
        }
        __syncthreads();
    }

#pragma unroll
    for (int mi = 0; mi < MT; mi++) {
        int row = m0 + wm0 + mi * 16 + gr;
#pragma unroll
        for (int ni = 0; ni < NT; ni++) {
            int col = n0 + wn0 + ni * 8 + lk * 2;
            if (col < Nv) {
                *(float2*)(Cout + (size_t)row * Nstride + col) =
                    make_float2(acc[mi][ni][0], acc[mi][ni][1]);
                *(float2*)(Cout + (size_t)(row + 8) * Nstride + col) =
                    make_float2(acc[mi][ni][2], acc[mi][ni][3]);
            }
        }
    }
}

// ---------------------------------------------------------------------------
// Fused: depthwise causal conv (width 4) + bias + SiLU, and dt/ldA prep
// ---------------------------------------------------------------------------
__global__ void conv_dt_kernel(const float* __restrict__ zx,
                               const float* __restrict__ cw,
                               const float* __restrict__ cb,
                               const float* __restrict__ dt_bias,
                               const float* __restrict__ A_log,
                               float* __restrict__ out,
                               float* __restrict__ dt_out,
                               float* __restrict__ ldA_out)
{
    int idx = blockIdx.x * blockDim.x + threadIdx.x;
    if (idx < BL * CONV_DIM) {
        int c  = idx % CONV_DIM;
        int bl = idx / CONV_DIM;
        int l  = bl % LL;
        int b  = bl / LL;

        float sum = cb[c];
#pragma unroll
        for (int j = 0; j < D_CONV; j++) {
            int t = l + j - (D_CONV - 1);
            if (t >= 0)
                sum = fmaf(zx[(size_t)(b * LL + t) * D_IN_PROJ + D_SSM + c],
                           cw[c * D_CONV + j], sum);
        }
        float sig = 1.f / (1.f + expf(-sum));
        out[idx] = sum * sig;
    } else if (idx < BL * CONV_DIM + BL * NHEADS) {
        int i2 = idx - BL * CONV_DIM;
        int h  = i2 % NHEADS;
        int bl = i2 / NHEADS;
        float raw = zx[(size_t)bl * D_IN_PROJ + DT_OFF + h] + dt_bias[h];
        float sp = fmaxf(raw, 0.f) + log1pf(expf(-fabsf(raw)));
        float dt = fminf(fmaxf(sp, 1e-6f), 1000.f);
        float A  = -expf(A_log[h]);
        dt_out[i2]  = dt;
        ldA_out[i2] = fmaxf(dt * A, LOG1EM6);
    }
}

// ---------------------------------------------------------------------------
// Chunk kernel (intra-chunk GEMMs + chunk summary) — tf32 tensor-core version
// 8 warps, warp grid 2(m) x 4(n): each warp owns a 32x16 output tile
// (MT=2 m16 tiles, NT=2 n8 tiles) of each 64x64 GEMM.
// ---------------------------------------------------------------------------
__global__ __launch_bounds__(256) void chunk_kernel(
    const float* __restrict__ xbc, const float* __restrict__ dtb,
    const float* __restrict__ lda, float* __restrict__ yintra,
    float* __restrict__ Tg, float* __restrict__ aig,
    float* __restrict__ laendg)
{
    extern __shared__ float sm[];
    float* sX  = sm;             // [64][65]  X (rows j, cols p)
    float* sB  = sm + 4160;      // [64][65]  B (rows j, cols n)
    float* sC  = sm + 8320;      // [64][65]  C (rows i, cols n); later G
    float* sdt = sm + 12480;
    float* sla = sdt + 64;
    float* sw  = sla + 64;

    const int bhc = blockIdx.x;
    const int c = bhc & (NCHUNK - 1);
    const int h = (bhc >> 3) % NHEADS;
    const int b = bhc / (NCHUNK * NHEADS);
    const int tid  = threadIdx.x;
    const int lane = tid & 31;
    const int warp = tid >> 5;
    const int gr   = lane >> 2;
    const int lk   = lane & 3;
    const int wm0  = (warp & 1) * 32;
    const int wn0  = (warp >> 1) * 16;
    const int row0 = b * LL + c * QC;

    // stage X, B, C tiles
#pragma unroll
    for (int idx = tid; idx < 64 * 16; idx += 256) {
        int i = idx >> 4, f = idx & 15;
        const float* rp = xbc + (size_t)(row0 + i) * CONV_DIM;
        float4 xv = *(const float4*)(rp + h * HEADDIM + f * 4);
        float4 bv = *(const float4*)(rp + D_SSM + f * 4);
        float4 cv = *(const float4*)(rp + D_SSM + D_STATE + f * 4);
        float* xr = sX + i * 65 + f * 4;
        xr[0] = xv.x; xr[1] = xv.y; xr[2] = xv.z; xr[3] = xv.w;
        float* br = sB + i * 65 + f * 4;
        br[0] = bv.x; br[1] = bv.y; br[2] = bv.z; br[3] = bv.w;
        float* cr = sC + i * 65 + f * 4;
        cr[0] = cv.x; cr[1] = cv.y; cr[2] = cv.z; cr[3] = cv.w;
    }
    if (tid < 64) {
        sdt[tid] = dtb[(row0 + tid) * NHEADS + h];
        sla[tid] = lda[(row0 + tid) * NHEADS + h];
    }
    __syncthreads();
    if (tid == 0) {
        float acc = 0.f;
#pragma unroll
        for (int i = 0; i < 64; i++) { acc += sla[i]; sla[i] = acc; }
    }
    __syncthreads();
    if (tid < 64) {
        sw[tid] = expf(sla[63] - sla[tid]) * sdt[tid];
        aig[bhc * QC + tid] = expf(sla[tid]);
        if (tid == 0) laendg[bhc] = sla[63];
    }

    // --- GEMM1: CB[i][j] = sum_n C[i,n] * B[j,n]  (A=C rows i, k=n; Bop[k=n][col=j]) ---
    float acc1[2][2][4];
#pragma unroll
    for (int mi = 0; mi < 2; mi++)
#pragma unroll
        for (int ni = 0; ni < 2; ni++)
#pragma unroll
            for (int e = 0; e < 4; e++) acc1[mi][ni][e] = 0.f;

#pragma unroll
    for (int k8 = 0; k8 < 8; k8++) {
        int kb = k8 * 8 + lk;
        uint32_t ua[2][4], ub[2][2];
#pragma unroll
        for (int mi = 0; mi < 2; mi++) {
            int r = wm0 + mi * 16 + gr;
            ua[mi][0] = f2tf(sC[r * 65 + kb]);
            ua[mi][1] = f2tf(sC[(r + 8) * 65 + kb]);
            ua[mi][2] = f2tf(sC[r * 65 + kb + 4]);
            ua[mi][3] = f2tf(sC[(r + 8) * 65 + kb + 4]);
        }
#pragma unroll
        for (int ni = 0; ni < 2; ni++) {
            int j = wn0 + ni * 8 + gr;
            ub[ni][0] = f2tf(sB[j * 65 + kb]);
            ub[ni][1] = f2tf(sB[j * 65 + kb + 4]);
        }
#pragma unroll
        for (int mi = 0; mi < 2; mi++)
#pragma unroll
            for (int ni = 0; ni < 2; ni++)
                mma8(acc1[mi][ni], ua[mi], ub[ni]);
    }
    __syncthreads();   // all warps done reading C before G overwrites it

    // mask + scale into G, store into sC
#pragma unroll
    for (int mi = 0; mi < 2; mi++) {
        int ilo = wm0 + mi * 16 + gr;
        int ihi = ilo + 8;
#pragma unroll
        for (int ni = 0; ni < 2; ni++) {
            int j0c = wn0 + ni * 8 + 2 * lk;
            int j1c = j0c + 1;
            float g00 = (j0c <= ilo) ? acc1[mi][ni][0] * sdt[j0c] * expf(sla[ilo] - sla[j0c]) : 0.f;
            float g01 = (j1c <= ilo) ? acc1[mi][ni][1] * sdt[j1c] * expf(sla[ilo] - sla[j1c]) : 0.f;
            float g10 = (j0c <= ihi) ? acc1[mi][ni][2] * sdt[j0c] * expf(sla[ihi] - sla[j0c]) : 0.f;
            float g11 = (j1c <= ihi) ? acc1[mi][ni][3] * sdt[j1c] * expf(sla[ihi] - sla[j1c]) : 0.f;
            sC[ilo * 65 + j0c] = g00;
            sC[ilo * 65 + j1c] = g01;
            sC[ihi * 65 + j0c] = g10;
            sC[ihi * 65 + j1c] = g11;
        }
    }
    __syncthreads();

    // --- GEMM2: Y[i][p] = sum_j G[i,j] * X[j,p]  (A=G rows i, k=j; Bop[k=j][col=p]) ---
    {
        float acc2[2][2][4];
#pragma unroll
        for (int mi = 0; mi < 2; mi++)
#pragma unroll
            for (int ni = 0; ni < 2; ni++)
#pragma unroll
                for (int e = 0; e < 4; e++) acc2[mi][ni][e] = 0.f;

#pragma unroll
        for (int k8 = 0; k8 < 8; k8++) {
            int kb = k8 * 8 + lk;
            uint32_t ua[2][4], ub[2][2];
#pragma unroll
            for (int mi = 0; mi < 2; mi++) {
                int r = wm0 + mi * 16 + gr;
                ua[mi][0] = f2tf(sC[r * 65 + kb]);
                ua[mi][1] = f2tf(sC[(r + 8) * 65 + kb]);
                ua[mi][2] = f2tf(sC[r * 65 + kb + 4]);
                ua[mi][3] = f2tf(sC[(r + 8) * 65 + kb + 4]);
            }
#pragma unroll
            for (int ni = 0; ni < 2; ni++) {
                int p = wn0 + ni * 8 + gr;
                ub[ni][0] = f2tf(sX[kb * 65 + p]);
                ub[ni][1] = f2tf(sX[(kb + 4) * 65 + p]);
            }
#pragma unroll
            for (int mi = 0; mi < 2; mi++)
#pragma unroll
                for (int ni = 0; ni < 2; ni++)
                    mma8(acc2[mi][ni], ua[mi], ub[ni]);
        }
#pragma unroll
        for (int mi = 0; mi < 2; mi++) {
            int ilo = wm0 + mi * 16 + gr;
#pragma unroll
            for (int ni = 0; ni < 2; ni++) {
                int pc = wn0 + ni * 8 + 2 * lk;
                *(float2*)(yintra + (size_t)(row0 + ilo) * D_SSM + h * HEADDIM + pc) =
                    make_float2(acc2[mi][ni][0], acc2[mi][ni][1]);
                *(float2*)(yintra + (size_t)(row0 + ilo + 8) * D_SSM + h * HEADDIM + pc) =
                    make_float2(acc2[mi][ni][2], acc2[mi][ni][3]);
            }
        }
    }

    // --- GEMM3: T[p][n] = sum_j (w_j * X[j,p]) * B[j,n] ---
    {
        float acc3[2][2][4];
#pragma unroll
        for (int mi = 0; mi < 2; mi++)
#pragma unroll
            for (int ni = 0; ni < 2; ni++)
#pragma unroll
                for (int e = 0; e < 4; e++) acc3[mi][ni][e] = 0.f;

#pragma unroll
        for (int k8 = 0; k8 < 8; k8++) {
            int kb = k8 * 8 + lk;
            float w0 = sw[kb], w1 = sw[kb + 4];
            uint32_t ua[2][4], ub[2][2];
#pragma unroll
            for (int mi = 0; mi < 2; mi++) {
                int r = wm0 + mi * 16 + gr;   // p index
                ua[mi][0] = f2tf(sX[kb * 65 + r] * w0);
                ua[mi][1] = f2tf(sX[kb * 65 + r + 8] * w0);
                ua[mi][2] = f2tf(sX[(kb + 4) * 65 + r] * w1);
                ua[mi][3] = f2tf(sX[(kb + 4) * 65 + r + 8] * w1);
            }
#pragma unroll
            for (int ni = 0; ni < 2; ni++) {
                int n = wn0 + ni * 8 + gr;
                ub[ni][0] = f2tf(sB[kb * 65 + n]);
                ub[ni][1] = f2tf(sB[(kb + 4) * 65 + n]);
            }
#pragma unroll
            for (int mi = 0; mi < 2; mi++)
#pragma unroll
                for (int ni = 0; ni < 2; ni++)
                    mma8(acc3[mi][ni], ua[mi], ub[ni]);
        }
#pragma unroll
        for (int mi = 0; mi < 2; mi++) {
            int plo = wm0 + mi * 16 + gr;
#pragma unroll
            for (int ni = 0; ni < 2; ni++) {
                int nc = wn0 + ni * 8 + 2 * lk;
                *(float2*)(Tg + (size_t)bhc * 4096 + plo * 64 + nc) =
                    make_float2(acc3[mi][ni][0], acc3[mi][ni][1]);
                *(float2*)(Tg + (size_t)bhc * 4096 + (plo + 8) * 64 + nc) =
                    make_float2(acc3[mi][ni][2], acc3[mi][ni][3]);
            }
        }
    }
}

// ---------------------------------------------------------------------------
// Sequential chunk-state combine
// ---------------------------------------------------------------------------
__global__ __launch_bounds__(256) void combine_kernel(
    const float* __restrict__ Tg, const float* __restrict__ laendg,
    float* __restrict__ Sg)
{
    const int bh = blockIdx.x;
    const int off = threadIdx.x * 16;
    float4 s[4];
#pragma unroll
    for (int k = 0; k < 4; k++) s[k] = make_float4(0.f, 0.f, 0.f, 0.f);

#pragma unroll
    for (int c = 0; c < NCHUNK; c++) {
        int bhc = bh * NCHUNK + c;
        float4* dst = (float4*)(Sg + (size_t)bhc * 4096 + off);
#pragma unroll
        for (int k = 0; k < 4; k++) dst[k] = s[k];
        float ae = expf(laendg[bhc]);
        const float4* tp = (const float4*)(Tg + (size_t)bhc * 4096 + off);
#pragma unroll
        for (int k = 0; k < 4; k++) {
            float4 t = tp[k];
            s[k].x = fmaf(ae, s[k].x, t.x);
            s[k].y = fmaf(ae, s[k].y, t.y);
            s[k].z = fmaf(ae, s[k].z, t.z);
            s[k].w = fmaf(ae, s[k].w, t.w);
        }
    }
}

// ---------------------------------------------------------------------------
// Inter-chunk contribution + skip + gating
// ---------------------------------------------------------------------------
__global__ __launch_bounds__(256) void inter_kernel(
    const float* __restrict__ xbc, const float* __restrict__ Sg,
    const float* __restrict__ aig, const float* __restrict__ zx,
    const float* __restrict__ Dp, float* __restrict__ y)
{
    __shared__ float sC[64 * 65];
    __shared__ float sS[64 * 65];
    __shared__ float sai[64];

    const int bhc = blockIdx.x;
    const int c = bhc & (NCHUNK - 1);
    const int h = (bhc >> 3) % NHEADS;
    const int b = bhc / (NCHUNK * NHEADS);
    const int tid = threadIdx.x;
    const int row0 = b * LL + c * QC;

#pragma unroll
    for (int idx = tid; idx < 64 * 16; idx += 256) {
        int i = idx >> 4, f = idx & 15;
        const float* rp = xbc + (size_t)(row0 + i) * CONV_DIM;
        float4 cv = *(const float4*)(rp + D_SSM + D_STATE + f * 4);
        float* cr = sC + i * 65 + f * 4;
        cr[0] = cv.x; cr[1] = cv.y; cr[2] = cv.z; cr[3] = cv.w;
        float4 sv = *(const float4*)(Sg + (size_t)bhc * 4096 + i * 64 + f * 4);
        float* sr = sS + i * 65 + f * 4;
        sr[0] = sv.x; sr[1] = sv.y; sr[2] = sv.z; sr[3] = sv.w;
    }
    if (tid < 64) sai[tid] = aig[bhc * QC + tid];
    __syncthreads();

    const int ti = tid >> 4, tj = tid & 15;
    const int i0 = ti * 4, p0 = tj * 4;

    float acc[4][4];
#pragma unroll
    for (int a = 0; a < 4; a++)
#pragma unroll
        for (int q = 0; q < 4; q++) acc[a][q] = 0.f;
#pragma unroll
    for (int n = 0; n < 64; n++) {
        float cv[4], sv[4];
#pragma unroll
        for (int a = 0; a < 4; a++) cv[a] = sC[(i0 + a) * 65 + n];
#pragma unroll
        for (int q = 0; q < 4; q++) sv[q] = sS[(p0 + q) * 65 + n];
#pragma unroll
        for (int a = 0; a < 4; a++)
#pragma unroll
            for (int q = 0; q < 4; q++)
                acc[a][q] = fmaf(cv[a], sv[q], acc[a][q]);
    }

    const float Dv = Dp[h];
#pragma unroll
    for (int a = 0; a < 4; a++) {
        int i = i0 + a;
        size_t r = row0 + i;
#pragma unroll
        for (int q = 0; q < 4; q++) {
            int p = p0 + q;
            float xv = xbc[r * CONV_DIM + h * HEADDIM + p];
            float zv = zx[r * D_IN_PROJ + h * HEADDIM + p];
            size_t yi = r * D_SSM + h * HEADDIM + p;
            float yv = y[yi] + sai[i] * acc[a][q] + Dv * xv;
            float sig = 1.f / (1.f + expf(-zv));
            y[yi] = yv * zv * sig;
        }
    }
}

// ---------------------------------------------------------------------------
// Launch
// ---------------------------------------------------------------------------
extern "C" void kernel_launch(void* const* d_in, const int* in_sizes, int n_in,
                              void* d_out, int out_size)
{
    const float* u       = (const float*)d_in[0];
    const float* W_in    = (const float*)d_in[1];
    const float* conv_w  = (const float*)d_in[2];
    const float* conv_b  = (const float*)d_in[3];
    const float* dt_bias = (const float*)d_in[4];
    const float* A_log   = (const float*)d_in[5];
    const float* D_param = (const float*)d_in[6];
    const float* W_out   = (const float*)d_in[7];
    float* out = (float*)d_out;

    float *zx, *xbc, *dt, *ldA, *y, *Tg, *Sg, *aig, *laendg;
    cudaGetSymbolAddress((void**)&zx,     g_zxbcdt);
    cudaGetSymbolAddress((void**)&xbc,    g_xbc);
    cudaGetSymbolAddress((void**)&dt,     g_dt);
    cudaGetSymbolAddress((void**)&ldA,    g_ldA);
    cudaGetSymbolAddress((void**)&y,      g_y);
    cudaGetSymbolAddress((void**)&Tg,     g_T);
    cudaGetSymbolAddress((void**)&Sg,     g_S);
    cudaGetSymbolAddress((void**)&aig,    g_ai);
    cudaGetSymbolAddress((void**)&laendg, g_laend);

    static bool attr_done = false;
    if (!attr_done) {
        cudaFuncSetAttribute(chunk_kernel,
                             cudaFuncAttributeMaxDynamicSharedMemorySize, 51200);
        cudaFuncSetAttribute(mma_gemm<128, 128>,
                             cudaFuncAttributeMaxDynamicSharedMemorySize, 73728);
        attr_done = true;
    }

    // 1) in_proj: z+x cols 1x tf32; B/C/dt block-cols (n0>=3072) tf32x3
    {
        dim3 grid(26, BL / 128);
        mma_gemm<128, 128><<<grid, 256, 73728>>>(
            u, W_in, zx, D_IN_PROJ, D_IN_PROJ, D_IN_PROJ, D_MODEL, 3072);
    }
    // 2) conv + silu + dt/ldA (fused)
    {
        int cnt = BL * CONV_DIM + BL * NHEADS;
        conv_dt_kernel<<<(cnt + 255) / 256, 256>>>(
            zx, conv_w, conv_b, dt_bias, A_log, xbc, dt, ldA);
    }
    // 3) chunked scan
    chunk_kernel<<<NBHC, 256, 51200>>>(xbc, dt, ldA, y, Tg, aig, laendg);
    combine_kernel<<<BB * NHEADS, 256>>>(Tg, laendg, Sg);
    inter_kernel<<<NBHC, 256>>>(xbc, Sg, aig, zx, D_param, y);

    // 4) out_proj: 1x tf32, 128x128 tiles
    {
        dim3 grid(D_MODEL / 128, BL / 128);
        mma_gemm<128, 128><<<grid, 256, 73728>>>(
            y, W_out, out, D_MODEL, D_MODEL, D_MODEL, D_SSM, 1 << 30);
    }
}